// round 3
// baseline (speedup 1.0000x reference)
#include <cuda_runtime.h>
#include <cuda_fp16.h>
#include <cstdint>

static constexpr int BM = 256;   // = M, so weight is read exactly once
static constexpr int BN = 128;
static constexpr int BK = 64;
static constexpr int THREADS = 512;
static constexpr int ASTRIDE = 80;   // smem bytes per row (16B multiple, 20 banks)

// Static scratch (allocation-free rule): quantized activations + per-token scales.
__device__ __align__(16) int8_t g_qx[256 * 8192];
__device__ float g_ascale[256];

// ---------------------------------------------------------------------------
// Runtime dtype classification. The harness stores inputs as one of
// {float32, int32, bfloat16}; f16 may or may not have been promoted.
// Returns 2 = bf16, 1 = f16, 0 = f32. Counts how many of the first 128
// 16-bit words are plausible under each interpretation.
// ---------------------------------------------------------------------------
__device__ __forceinline__ int classify16(const uint16_t* p, float lo, float hi) {
    int cbf = 0, cf16 = 0;
    #pragma unroll 8
    for (int i = 0; i < 128; i++) {
        uint32_t u = p[i];
        float vb = __uint_as_float(u << 16);            // as bf16
        float ab = fabsf(vb);
        if (ab >= lo && ab <= hi) cbf++;
        float vh = __half2float(__ushort_as_half((unsigned short)u));  // as f16
        float ah = fabsf(vh);
        if (ah >= lo && ah <= hi) cf16++;
    }
    if (cbf  >= 96) return 2;
    if (cf16 >= 96) return 1;
    return 0;
}

__device__ __forceinline__ bool weight_is_i32(const void* w) {
    const int* wi = (const int*)w;
    bool all = true;
    #pragma unroll
    for (int j = 0; j < 8; j++) {
        int v = wi[j];
        all = all && (v >= -128 && v <= 127);
    }
    return all;
}

// pack low bytes of 4 int32 -> one uint32 (bytes in order x,y,z,w)
__device__ __forceinline__ uint32_t pack4(uint4 v) {
    uint32_t t0 = __byte_perm(v.x, v.y, 0x0040);  // [x0, y0, -, -]
    uint32_t t1 = __byte_perm(v.z, v.w, 0x0040);  // [z0, w0, -, -]
    return __byte_perm(t0, t1, 0x5410);           // [x0, y0, z0, w0]
}

// ---------------------------------------------------------------------------
// Kernel 1: per-token symmetric int8 quantization (matches quant_act exactly).
// One block per token. MODE: 0 = x is f32, 1 = f16, 2 = bf16. Wrong-mode
// instantiations early-exit.
// ---------------------------------------------------------------------------
template <int MODE>
__global__ void __launch_bounds__(256) quant_kernel(const void* __restrict__ xv,
                                                    int K) {
    if (classify16((const uint16_t*)xv, 0.05f, 30.0f) != MODE) return;

    const int m   = blockIdx.x;
    const int tid = threadIdx.x;

    float vals[32];   // 4 iters * 8 values (K = 8192, 256 threads)
    float mx = 0.f;

    #pragma unroll
    for (int i = 0; i < 4; i++) {
        float f[8];
        if (MODE == 0) {
            const uint4* x4 = (const uint4*)((const float*)xv + (size_t)m * K);
            uint4 v0 = x4[(i * 256 + tid) * 2];
            uint4 v1 = x4[(i * 256 + tid) * 2 + 1];
            f[0] = __uint_as_float(v0.x); f[1] = __uint_as_float(v0.y);
            f[2] = __uint_as_float(v0.z); f[3] = __uint_as_float(v0.w);
            f[4] = __uint_as_float(v1.x); f[5] = __uint_as_float(v1.y);
            f[6] = __uint_as_float(v1.z); f[7] = __uint_as_float(v1.w);
        } else {
            const uint4* x4 = (const uint4*)((const uint16_t*)xv + (size_t)m * K);
            uint4 v = x4[i * 256 + tid];
            uint32_t w[4] = {v.x, v.y, v.z, v.w};
            #pragma unroll
            for (int j = 0; j < 4; j++) {
                uint32_t lo = w[j] & 0xFFFFu, hi = w[j] >> 16;
                if (MODE == 1) {
                    f[j * 2]     = __half2float(__ushort_as_half((unsigned short)lo));
                    f[j * 2 + 1] = __half2float(__ushort_as_half((unsigned short)hi));
                } else {
                    f[j * 2]     = __uint_as_float(lo << 16);
                    f[j * 2 + 1] = __uint_as_float(hi << 16);
                }
            }
        }
        #pragma unroll
        for (int j = 0; j < 8; j++) {
            vals[i * 8 + j] = f[j];
            mx = fmaxf(mx, fabsf(f[j]));
        }
    }

    __shared__ float red[32];
    #pragma unroll
    for (int o = 16; o > 0; o >>= 1)
        mx = fmaxf(mx, __shfl_xor_sync(0xffffffffu, mx, o));
    int warp = tid >> 5, lane = tid & 31;
    if (lane == 0) red[warp] = mx;
    __syncthreads();
    if (warp == 0) {
        float v = (lane < 8) ? red[lane] : 0.f;
        #pragma unroll
        for (int o = 4; o > 0; o >>= 1)
            v = fmaxf(v, __shfl_xor_sync(0xffffffffu, v, o));
        if (lane == 0) {
            float scale = fmaxf(v, 1e-5f) / 127.0f;
            red[0] = scale;
            g_ascale[m] = scale;
        }
    }
    __syncthreads();
    const float scale = red[0];

    int8_t* qr = g_qx + (size_t)m * K;
    #pragma unroll
    for (int i = 0; i < 4; i++) {
        uint32_t packed[2];
        int8_t* pb = reinterpret_cast<int8_t*>(packed);
        #pragma unroll
        for (int j = 0; j < 8; j++) {
            int q = __float2int_rn(__fdiv_rn(vals[i * 8 + j], scale));  // IEEE div + RN-even
            q = max(-127, min(127, q));
            pb[j] = (int8_t)q;
        }
        reinterpret_cast<uint2*>(qr)[i * 256 + tid] = make_uint2(packed[0], packed[1]);
    }
}

// ---------------------------------------------------------------------------
// Kernel 2: int8 GEMM [256,K] x [N,K]^T -> int32, fused dequant epilogue.
// WI32 = weight stored as int32 (harness-promoted) vs native int8.
// mma.sync.m16n8k32.s8. 512 threads, BM=256 x BN=128 x BK=64.
// ---------------------------------------------------------------------------
template <bool WI32>
__global__ void __launch_bounds__(THREADS, 1) gemm_kernel(
    const void* __restrict__ Wv,
    const float* __restrict__ scale_channel,
    const void* __restrict__ p_bias,
    float* __restrict__ out,
    int N, int K)
{
    if (weight_is_i32(Wv) != WI32) return;

    __shared__ __align__(128) int8_t sA[BM * ASTRIDE];
    __shared__ __align__(128) int8_t sB[BN * ASTRIDE];
    __shared__ float s_scale[BN];
    __shared__ float s_bias[BN];

    const int tid  = threadIdx.x;
    const int bn   = blockIdx.x;
    const int warp = tid >> 5;
    const int lane = tid & 31;
    const int wm   = warp & 7;   // 8 warps along M (8*32 = 256)
    const int wn   = warp >> 3;  // 2 warps along N (2*64 = 128)

    const int8_t* gA = g_qx;

    int acc[2][8][4];
    #pragma unroll
    for (int i = 0; i < 2; i++)
        #pragma unroll
        for (int j = 0; j < 8; j++)
            #pragma unroll
            for (int l = 0; l < 4; l++) acc[i][j][l] = 0;

    const int ld_row   = tid >> 2;        // 0..127
    const int ld_chunk = (tid & 3) * 16;  // element offset within BK

    uint4 ra[2], rw[4];

    const int8_t* gB8  = (const int8_t*)Wv;
    const int*    gB32 = (const int*)Wv;
    const size_t  nrow = (size_t)(bn * BN + ld_row) * K;

    auto ldg = [&](int k0) {
        ra[0] = *reinterpret_cast<const uint4*>(gA + (size_t)ld_row         * K + k0 + ld_chunk);
        ra[1] = *reinterpret_cast<const uint4*>(gA + (size_t)(ld_row + 128) * K + k0 + ld_chunk);
        if (WI32) {
            #pragma unroll
            for (int j = 0; j < 4; j++)
                rw[j] = *reinterpret_cast<const uint4*>(gB32 + nrow + k0 + ld_chunk + j * 4);
        } else {
            rw[0] = *reinterpret_cast<const uint4*>(gB8 + nrow + k0 + ld_chunk);
        }
    };
    auto sts = [&]() {
        *reinterpret_cast<uint4*>(&sA[ld_row * ASTRIDE + ld_chunk])         = ra[0];
        *reinterpret_cast<uint4*>(&sA[(ld_row + 128) * ASTRIDE + ld_chunk]) = ra[1];
        if (WI32) {
            uint4 p = make_uint4(pack4(rw[0]), pack4(rw[1]), pack4(rw[2]), pack4(rw[3]));
            *reinterpret_cast<uint4*>(&sB[ld_row * ASTRIDE + ld_chunk]) = p;
        } else {
            *reinterpret_cast<uint4*>(&sB[ld_row * ASTRIDE + ld_chunk]) = rw[0];
        }
    };

    const int NK = K / BK;
    ldg(0);

    for (int kt = 0; kt < NK; kt++) {
        __syncthreads();
        sts();
        __syncthreads();
        if (kt + 1 < NK) ldg((kt + 1) * BK);

        #pragma unroll
        for (int kc = 0; kc < 2; kc++) {
            const int boff = kc * 32 + (lane & 3) * 4;
            uint32_t a[2][4];
            #pragma unroll
            for (int mt = 0; mt < 2; mt++) {
                int row0 = wm * 32 + mt * 16 + (lane >> 2);
                a[mt][0] = *(const uint32_t*)(sA + row0 * ASTRIDE + boff);
                a[mt][1] = *(const uint32_t*)(sA + (row0 + 8) * ASTRIDE + boff);
                a[mt][2] = *(const uint32_t*)(sA + row0 * ASTRIDE + boff + 16);
                a[mt][3] = *(const uint32_t*)(sA + (row0 + 8) * ASTRIDE + boff + 16);
            }
            #pragma unroll
            for (int nt = 0; nt < 8; nt++) {
                int col = wn * 64 + nt * 8 + (lane >> 2);
                uint32_t b0 = *(const uint32_t*)(sB + col * ASTRIDE + boff);
                uint32_t b1 = *(const uint32_t*)(sB + col * ASTRIDE + boff + 16);
                #pragma unroll
                for (int mt = 0; mt < 2; mt++) {
                    asm volatile(
                        "mma.sync.aligned.m16n8k32.row.col.s32.s8.s8.s32 "
                        "{%0,%1,%2,%3}, {%4,%5,%6,%7}, {%8,%9}, {%0,%1,%2,%3};\n"
                        : "+r"(acc[mt][nt][0]), "+r"(acc[mt][nt][1]),
                          "+r"(acc[mt][nt][2]), "+r"(acc[mt][nt][3])
                        : "r"(a[mt][0]), "r"(a[mt][1]), "r"(a[mt][2]), "r"(a[mt][3]),
                          "r"(b0), "r"(b1));
                }
            }
        }
    }

    // Stage per-channel scale + bias (bias dtype detected at runtime).
    __syncthreads();
    {
        int bmode = classify16((const uint16_t*)p_bias, 2e-4f, 0.5f);
        if (tid < BN) {
            int g = bn * BN + tid;
            s_scale[tid] = scale_channel[g];
            float b;
            if (bmode == 0)      b = ((const float*)p_bias)[g];
            else if (bmode == 1) b = __half2float(((const __half*)p_bias)[g]);
            else                 b = __uint_as_float(((uint32_t)((const uint16_t*)p_bias)[g]) << 16);
            s_bias[tid] = b;
        }
    }
    __syncthreads();

    // Fused dequant epilogue: out = acc * act_scale[m] * scale_channel[n] + bias[n]
    #pragma unroll
    for (int mt = 0; mt < 2; mt++) {
        int row0 = wm * 32 + mt * 16 + (lane >> 2);
        float s0 = g_ascale[row0];
        float s1 = g_ascale[row0 + 8];
        #pragma unroll
        for (int nt = 0; nt < 8; nt++) {
            int lc = wn * 64 + nt * 8 + (lane & 3) * 2;
            float sc0 = s_scale[lc], sc1 = s_scale[lc + 1];
            float b0  = s_bias[lc],  b1  = s_bias[lc + 1];
            int gcol = bn * BN + lc;
            float2 v0, v1;
            v0.x = (float)acc[mt][nt][0] * s0 * sc0 + b0;
            v0.y = (float)acc[mt][nt][1] * s0 * sc1 + b1;
            v1.x = (float)acc[mt][nt][2] * s1 * sc0 + b0;
            v1.y = (float)acc[mt][nt][3] * s1 * sc1 + b1;
            *reinterpret_cast<float2*>(out + (size_t)row0 * N + gcol)       = v0;
            *reinterpret_cast<float2*>(out + (size_t)(row0 + 8) * N + gcol) = v1;
        }
    }
}

// ---------------------------------------------------------------------------
extern "C" void kernel_launch(void* const* d_in, const int* in_sizes, int n_in,
                              void* d_out, int out_size) {
    const void*  x    = d_in[0];
    const void*  w    = d_in[1];
    const float* sc   = (const float*)d_in[2];
    const void*  bias = d_in[3];
    float* out = (float*)d_out;

    const int N = in_sizes[2];            // 28672
    const int K = in_sizes[1] / N;        // 8192
    const int M = in_sizes[0] / K;        // 256

    // All three dtype variants launch; two early-exit after a uniform check.
    quant_kernel<0><<<M, 256>>>(x, K);
    quant_kernel<1><<<M, 256>>>(x, K);
    quant_kernel<2><<<M, 256>>>(x, K);

    dim3 grid(N / BN);
    gemm_kernel<true ><<<grid, THREADS>>>(w, sc, bias, out, N, K);
    gemm_kernel<false><<<grid, THREADS>>>(w, sc, bias, out, N, K);
}

// round 5
// speedup vs baseline: 1.0408x; 1.0408x over previous
#include <cuda_runtime.h>
#include <cuda_fp16.h>
#include <cstdint>

static constexpr int BM = 256;        // = M: weight read exactly once
static constexpr int BN = 112;        // 28672/112 = 256 CTAs -> 2 balanced waves
static constexpr int BK = 128;
static constexpr int THREADS = 512;

static constexpr int A_STRIDE = 144;  // 128 + 16 pad (bank step 4)
static constexpr int W_STRIDE = 528;  // 512 + 16 pad (raw int32 rows)
static constexpr int A_BYTES  = BM * A_STRIDE;          // 36864
static constexpr int W_BYTES  = BN * W_STRIDE;          // 59136
static constexpr int SM_HDR   = 1024;
static constexpr int SM_STAGE = A_BYTES + W_BYTES;      // 96000
static constexpr int SM_TOTAL = SM_HDR + 2 * SM_STAGE;  // 193024

// Static scratch: quantized activations + per-token scales.
__device__ __align__(16) int8_t g_qx[256 * 8192];
__device__ float g_ascale[256];

__device__ __forceinline__ uint32_t smem_u32(const void* p) {
    return (uint32_t)__cvta_generic_to_shared(p);
}
__device__ __forceinline__ uint32_t pack4(uint4 v) {
    uint32_t t0 = __byte_perm(v.x, v.y, 0x0040);
    uint32_t t1 = __byte_perm(v.z, v.w, 0x0040);
    return __byte_perm(t0, t1, 0x5410);
}

// ---------------------------------------------------------------------------
// dtype detection (verified in round 3)
// ---------------------------------------------------------------------------
__device__ __forceinline__ int classify16(const uint16_t* p, float lo, float hi) {
    int cbf = 0, cf16 = 0;
    #pragma unroll 8
    for (int i = 0; i < 128; i++) {
        uint32_t u = p[i];
        float vb = __uint_as_float(u << 16);
        float ab = fabsf(vb);
        if (ab >= lo && ab <= hi) cbf++;
        float vh = __half2float(__ushort_as_half((unsigned short)u));
        float ah = fabsf(vh);
        if (ah >= lo && ah <= hi) cf16++;
    }
    if (cbf  >= 96) return 2;
    if (cf16 >= 96) return 1;
    return 0;
}
__device__ __forceinline__ bool weight_is_i32(const void* w) {
    const int* wi = (const int*)w;
    bool all = true;
    #pragma unroll
    for (int j = 0; j < 8; j++) {
        int v = wi[j];
        all = all && (v >= -128 && v <= 127);
    }
    return all;
}

// ---------------------------------------------------------------------------
// Kernel 1: per-token int8 quantization (verified, unchanged)
// ---------------------------------------------------------------------------
template <int MODE>
__global__ void __launch_bounds__(256) quant_kernel(const void* __restrict__ xv,
                                                    int K) {
    if (classify16((const uint16_t*)xv, 0.05f, 30.0f) != MODE) return;

    const int m   = blockIdx.x;
    const int tid = threadIdx.x;

    float vals[32];
    float mx = 0.f;

    #pragma unroll
    for (int i = 0; i < 4; i++) {
        float f[8];
        if (MODE == 0) {
            const uint4* x4 = (const uint4*)((const float*)xv + (size_t)m * K);
            uint4 v0 = x4[(i * 256 + tid) * 2];
            uint4 v1 = x4[(i * 256 + tid) * 2 + 1];
            f[0] = __uint_as_float(v0.x); f[1] = __uint_as_float(v0.y);
            f[2] = __uint_as_float(v0.z); f[3] = __uint_as_float(v0.w);
            f[4] = __uint_as_float(v1.x); f[5] = __uint_as_float(v1.y);
            f[6] = __uint_as_float(v1.z); f[7] = __uint_as_float(v1.w);
        } else {
            const uint4* x4 = (const uint4*)((const uint16_t*)xv + (size_t)m * K);
            uint4 v = x4[i * 256 + tid];
            uint32_t w[4] = {v.x, v.y, v.z, v.w};
            #pragma unroll
            for (int j = 0; j < 4; j++) {
                uint32_t lo = w[j] & 0xFFFFu, hi = w[j] >> 16;
                if (MODE == 1) {
                    f[j * 2]     = __half2float(__ushort_as_half((unsigned short)lo));
                    f[j * 2 + 1] = __half2float(__ushort_as_half((unsigned short)hi));
                } else {
                    f[j * 2]     = __uint_as_float(lo << 16);
                    f[j * 2 + 1] = __uint_as_float(hi << 16);
                }
            }
        }
        #pragma unroll
        for (int j = 0; j < 8; j++) {
            vals[i * 8 + j] = f[j];
            mx = fmaxf(mx, fabsf(f[j]));
        }
    }

    __shared__ float red[32];
    #pragma unroll
    for (int o = 16; o > 0; o >>= 1)
        mx = fmaxf(mx, __shfl_xor_sync(0xffffffffu, mx, o));
    int warp = tid >> 5, lane = tid & 31;
    if (lane == 0) red[warp] = mx;
    __syncthreads();
    if (warp == 0) {
        float v = (lane < 8) ? red[lane] : 0.f;
        #pragma unroll
        for (int o = 4; o > 0; o >>= 1)
            v = fmaxf(v, __shfl_xor_sync(0xffffffffu, v, o));
        if (lane == 0) {
            float scale = fmaxf(v, 1e-5f) / 127.0f;
            red[0] = scale;
            g_ascale[m] = scale;
        }
    }
    __syncthreads();
    const float scale = red[0];

    int8_t* qr = g_qx + (size_t)m * K;
    #pragma unroll
    for (int i = 0; i < 4; i++) {
        uint32_t packed[2];
        int8_t* pb = reinterpret_cast<int8_t*>(packed);
        #pragma unroll
        for (int j = 0; j < 8; j++) {
            int q = __float2int_rn(__fdiv_rn(vals[i * 8 + j], scale));
            q = max(-127, min(127, q));
            pb[j] = (int8_t)q;
        }
        reinterpret_cast<uint2*>(qr)[i * 256 + tid] = make_uint2(packed[0], packed[1]);
    }
}

// ---------------------------------------------------------------------------
// Kernel 2: int8 GEMM [256,K] x [N,K]^T -> int32, mma.sync.m16n8k32.
// cp.async double-buffered; W kept raw (int32) in smem, packed in-register
// at fragment-load time. Fused dequant epilogue.
// ---------------------------------------------------------------------------
template <bool WI32>
__global__ void __launch_bounds__(THREADS, 1) gemm_kernel(
    const void* __restrict__ Wv,
    const float* __restrict__ scale_channel,
    const void* __restrict__ p_bias,
    float* __restrict__ out,
    int N, int K)
{
    if (weight_is_i32(Wv) != WI32) return;

    extern __shared__ char smem[];
    const int tid  = threadIdx.x;
    const int warp = tid >> 5;
    const int lane = tid & 31;
    const int bn   = blockIdx.x;
    const int wm   = warp & 7;   // 8 warps along M: 8*32 = 256
    const int wn   = warp >> 3;  // 2 warps along N: 2*56 = 112

    const char* gW = (const char*)Wv;
    const int   wELT = WI32 ? 4 : 1;          // bytes per weight element in gmem

    int acc[2][7][4];
    #pragma unroll
    for (int i = 0; i < 2; i++)
        #pragma unroll
        for (int j = 0; j < 7; j++)
            #pragma unroll
            for (int l = 0; l < 4; l++) acc[i][j][l] = 0;

    // ---- cp.async tile loader: A (int8) + W (raw int8/int32) ----
    auto cp_tile = [&](int kt, int st) {
        char* aBase = smem + SM_HDR + st * SM_STAGE;
        char* wBase = aBase + A_BYTES;
        const int k0 = kt * BK;

        // A: 256 rows x 128B = 2048 chunks of 16B
        #pragma unroll
        for (int i = 0; i < 4; i++) {
            int task = tid + i * THREADS;
            int row  = task >> 3;
            int ch   = (task & 7) * 16;
            uint32_t dst = smem_u32(aBase + row * A_STRIDE + ch);
            const int8_t* src = g_qx + (size_t)row * K + k0 + ch;
            asm volatile("cp.async.cg.shared.global [%0], [%1], 16;\n"
                         :: "r"(dst), "l"(src));
        }
        // W: 112 rows x (128*wELT) bytes
        const int rowBytes = BK * wELT;                  // 512 or 128
        const int chunks   = rowBytes / 16;              // 32 or 8
        const int tasks    = BN * chunks;                // 3584 or 896
        for (int task = tid; task < tasks; task += THREADS) {
            int row = task / chunks;
            int ch  = (task % chunks) * 16;
            uint32_t dst = smem_u32(wBase + row * W_STRIDE + ch);
            const char* src = gW + ((size_t)(bn * BN + row) * K + k0) * wELT + ch;
            asm volatile("cp.async.cg.shared.global [%0], [%1], 16;\n"
                         :: "r"(dst), "l"(src));
        }
        asm volatile("cp.async.commit_group;\n");
    };

    const int NK = K / BK;   // 64
    cp_tile(0, 0);
    cp_tile(1, 1);

    for (int kt = 0; kt < NK; kt++) {
        if (kt + 2 < NK) asm volatile("cp.async.wait_group 1;\n");
        else             asm volatile("cp.async.wait_group 0;\n");
        __syncthreads();

        const char* sA = smem + SM_HDR + (kt & 1) * SM_STAGE;
        const char* sW = sA + A_BYTES;

        #pragma unroll
        for (int kc = 0; kc < 4; kc++) {
            const int aofs = kc * 32 + (lane & 3) * 4;
            uint32_t a[2][4];
            #pragma unroll
            for (int mt = 0; mt < 2; mt++) {
                int row0 = wm * 32 + mt * 16 + (lane >> 2);
                a[mt][0] = *(const uint32_t*)(sA + row0 * A_STRIDE + aofs);
                a[mt][1] = *(const uint32_t*)(sA + (row0 + 8) * A_STRIDE + aofs);
                a[mt][2] = *(const uint32_t*)(sA + row0 * A_STRIDE + aofs + 16);
                a[mt][3] = *(const uint32_t*)(sA + (row0 + 8) * A_STRIDE + aofs + 16);
            }
            #pragma unroll
            for (int nt = 0; nt < 7; nt++) {
                int r = wn * 56 + nt * 8 + (lane >> 2);
                uint32_t b0, b1;
                if (WI32) {
                    const char* base = sW + r * W_STRIDE + kc * 128 + (lane & 3) * 16;
                    uint4 v0 = *(const uint4*)(base);
                    uint4 v1 = *(const uint4*)(base + 64);
                    b0 = pack4(v0);
                    b1 = pack4(v1);
                } else {
                    b0 = *(const uint32_t*)(sW + r * W_STRIDE + aofs);
                    b1 = *(const uint32_t*)(sW + r * W_STRIDE + aofs + 16);
                }
                #pragma unroll
                for (int mt = 0; mt < 2; mt++) {
                    asm volatile(
                        "mma.sync.aligned.m16n8k32.row.col.s32.s8.s8.s32 "
                        "{%0,%1,%2,%3}, {%4,%5,%6,%7}, {%8,%9}, {%0,%1,%2,%3};\n"
                        : "+r"(acc[mt][nt][0]), "+r"(acc[mt][nt][1]),
                          "+r"(acc[mt][nt][2]), "+r"(acc[mt][nt][3])
                        : "r"(a[mt][0]), "r"(a[mt][1]), "r"(a[mt][2]), "r"(a[mt][3]),
                          "r"(b0), "r"(b1));
                }
            }
        }

        __syncthreads();
        if (kt + 2 < NK) cp_tile(kt + 2, kt & 1);
    }

    // ---- stage per-channel scale + bias ----
    float* s_scale = (float*)(smem);
    float* s_bias  = (float*)(smem + 512);
    {
        int bmode = classify16((const uint16_t*)p_bias, 2e-4f, 0.5f);
        if (tid < BN) {
            int g = bn * BN + tid;
            s_scale[tid] = scale_channel[g];
            float b;
            if (bmode == 0)      b = ((const float*)p_bias)[g];
            else if (bmode == 1) b = __half2float(((const __half*)p_bias)[g]);
            else                 b = __uint_as_float(((uint32_t)((const uint16_t*)p_bias)[g]) << 16);
            s_bias[tid] = b;
        }
    }
    __syncthreads();

    // ---- fused dequant epilogue ----
    #pragma unroll
    for (int mt = 0; mt < 2; mt++) {
        int row0 = wm * 32 + mt * 16 + (lane >> 2);
        float s0 = g_ascale[row0];
        float s1 = g_ascale[row0 + 8];
        #pragma unroll
        for (int nt = 0; nt < 7; nt++) {
            int lc = wn * 56 + nt * 8 + (lane & 3) * 2;
            float sc0 = s_scale[lc], sc1 = s_scale[lc + 1];
            float b0  = s_bias[lc],  b1  = s_bias[lc + 1];
            int gcol = bn * BN + lc;
            float2 v0, v1;
            v0.x = (float)acc[mt][nt][0] * s0 * sc0 + b0;
            v0.y = (float)acc[mt][nt][1] * s0 * sc1 + b1;
            v1.x = (float)acc[mt][nt][2] * s1 * sc0 + b0;
            v1.y = (float)acc[mt][nt][3] * s1 * sc1 + b1;
            *reinterpret_cast<float2*>(out + (size_t)row0 * N + gcol)       = v0;
            *reinterpret_cast<float2*>(out + (size_t)(row0 + 8) * N + gcol) = v1;
        }
    }
}

// ---------------------------------------------------------------------------
extern "C" void kernel_launch(void* const* d_in, const int* in_sizes, int n_in,
                              void* d_out, int out_size) {
    const void*  x    = d_in[0];
    const void*  w    = d_in[1];
    const float* sc   = (const float*)d_in[2];
    const void*  bias = d_in[3];
    float* out = (float*)d_out;

    const int N = in_sizes[2];            // 28672
    const int K = in_sizes[1] / N;        // 8192
    const int M = in_sizes[0] / K;        // 256

    quant_kernel<0><<<M, 256>>>(x, K);
    quant_kernel<1><<<M, 256>>>(x, K);
    quant_kernel<2><<<M, 256>>>(x, K);

    cudaFuncSetAttribute(gemm_kernel<true >, cudaFuncAttributeMaxDynamicSharedMemorySize, SM_TOTAL);
    cudaFuncSetAttribute(gemm_kernel<false>, cudaFuncAttributeMaxDynamicSharedMemorySize, SM_TOTAL);

    dim3 grid(N / BN);                    // 256 CTAs
    gemm_kernel<true ><<<grid, THREADS, SM_TOTAL>>>(w, sc, bias, out, N, K);
    gemm_kernel<false><<<grid, THREADS, SM_TOTAL>>>(w, sc, bias, out, N, K);
}